// round 16
// baseline (speedup 1.0000x reference)
#include <cuda_runtime.h>
#include <cuda_fp16.h>
#include <cstdint>

#define N_NODE   100000
#define NODE_PAD 100096
#define D_IN     256
#define D_OUT    64
#define E_MAX    1600000
#define NEG_SLOPE 0.2f
#define SLD 72   // smem row stride in fp16 elems (144B) for 64-wide k stages

// ---- scratch (__device__ globals; no allocation at runtime) ----
__device__ __half g_xlh[NODE_PAD * D_IN];   // emb @ W_l, fp16
__device__ __half g_xrh[NODE_PAD * D_IN];   // emb @ W_r, fp16
__device__ __half g_Af[NODE_PAD * D_IN];    // emb, fp16
__device__ __half g_Bf[512 * 256];          // rows 0-255: Wl^T, 256-511: Wr^T ([n][k])
__device__ int   g_cnt[N_NODE];
__device__ int   g_incl[N_NODE];
__device__ int   g_cursor[N_NODE];
__device__ int   g_srcs[E_MAX];
__device__ int   g_bsum[256];

// ============================================================
// Prep: fp32 -> fp16
// ============================================================
__global__ void prepA_k(const float4* __restrict__ emb4, int n4, int np4)
{
    int i = blockIdx.x * blockDim.x + threadIdx.x;
    if (i >= np4) return;
    float4 v = (i < n4) ? emb4[i] : make_float4(0.f, 0.f, 0.f, 0.f);
    __half2* hp = (__half2*)g_Af;
    hp[2 * i]     = __floats2half2_rn(v.x, v.y);
    hp[2 * i + 1] = __floats2half2_rn(v.z, v.w);
}

__global__ void prepW_k(const float* __restrict__ Wl, const float* __restrict__ Wr)
{
    int idx = blockIdx.x * blockDim.x + threadIdx.x;   // 512*256
    if (idx >= 512 * 256) return;
    int n = idx >> 8, k = idx & 255;
    float v = (n < 256) ? Wl[k * 256 + n] : Wr[k * 256 + (n - 256)];
    g_Bf[idx] = __float2half_rn(v);
}

// ============================================================
// mma.sync fp16 GEMM, cp.async double-buffered (64-wide k stages),
// ldmatrix frags. C[NODE_PAD,512] = A x [Wl|Wr]^T, fp32 accum.
// CTA 128m x 128n, 4 warps of 64x64 (2x2), 2 CTAs/SM.
// ============================================================
__device__ __forceinline__ void mma16816(float c[4], const uint32_t a[4],
                                         const uint32_t b0, const uint32_t b1)
{
    asm volatile(
        "mma.sync.aligned.m16n8k16.row.col.f32.f16.f16.f32 "
        "{%0,%1,%2,%3}, {%4,%5,%6,%7}, {%8,%9}, {%0,%1,%2,%3};"
        : "+f"(c[0]), "+f"(c[1]), "+f"(c[2]), "+f"(c[3])
        : "r"(a[0]), "r"(a[1]), "r"(a[2]), "r"(a[3]), "r"(b0), "r"(b1));
}

__device__ __forceinline__ void ldsm4(uint32_t r[4], uint32_t addr)
{
    asm volatile("ldmatrix.sync.aligned.m8n8.x4.shared.b16 {%0,%1,%2,%3}, [%4];"
                 : "=r"(r[0]), "=r"(r[1]), "=r"(r[2]), "=r"(r[3]) : "r"(addr));
}

__device__ __forceinline__ void cpa16(uint32_t dst, const void* src)
{
    asm volatile("cp.async.ca.shared.global [%0], [%1], 16;"
                 :: "r"(dst), "l"(src));
}

#define TILE_MAT (128 * SLD * 2)   // 18432 B per matrix tile (128 rows x 64 k)
#define STAGE_B  (2 * TILE_MAT)    // 36864 B (A + B)
#define OFF_A 0
#define OFF_B TILE_MAT

__global__ void __launch_bounds__(128, 2)
gemm_mma()
{
    extern __shared__ __align__(16) char smem[];
    uint32_t sb;
    asm("{ .reg .u64 t; cvta.to.shared.u64 t, %1; cvt.u32.u64 %0, t; }"
        : "=r"(sb) : "l"(smem));

    const int tid = threadIdx.x;
    const int wid = tid >> 5;          // 0..3
    const int lane = tid & 31;
    const int g = lane >> 2;
    const int t = lane & 3;
    const int m0 = blockIdx.y * 128;
    const int n0 = blockIdx.x * 128;
    const int wm = (wid & 1) * 64;     // warp row base
    const int wn = (wid >> 1) * 64;    // warp col base

    float acc[4][8][4];
#pragma unroll
    for (int i = 0; i < 4; i++)
#pragma unroll
        for (int j = 0; j < 8; j++)
#pragma unroll
            for (int q = 0; q < 4; q++) acc[i][j][q] = 0.f;

    // stage: 128 rows x 64 fp16 per matrix = 1024 uint4; 8 chunks/thread
    auto stage_load = [&](int s, int kt) {
        uint32_t st = sb + s * STAGE_B;
#pragma unroll
        for (int i = 0; i < 8; i++) {
            int idx = tid + i * 128;
            int r = idx >> 3, q = idx & 7;
            size_t ga = (size_t)(m0 + r) * 256 + kt * 64 + q * 8;
            size_t gb = (size_t)(n0 + r) * 256 + kt * 64 + q * 8;
            uint32_t so = (uint32_t)(r * SLD + q * 8) * 2;
            cpa16(st + OFF_A + so, g_Af + ga);
            cpa16(st + OFF_B + so, g_Bf + gb);
        }
        asm volatile("cp.async.commit_group;" ::: "memory");
    };

    stage_load(0, 0);

    for (int kt = 0; kt < 4; kt++) {
        if (kt < 3) {
            stage_load((kt + 1) & 1, kt + 1);
            asm volatile("cp.async.wait_group 1;" ::: "memory");
        } else {
            asm volatile("cp.async.wait_group 0;" ::: "memory");
        }
        __syncthreads();

        uint32_t st = sb + (kt & 1) * STAGE_B;
        uint32_t bA = st + OFF_A, bB = st + OFF_B;

#pragma unroll
        for (int kk = 0; kk < 64; kk += 16) {
            uint32_t ah[4][4];
            int arow = (lane & 15);
            int akch = kk + ((lane >> 4) << 3);
#pragma unroll
            for (int mi = 0; mi < 4; mi++) {
                uint32_t ao = (uint32_t)((wm + mi * 16 + arow) * SLD + akch) * 2;
                ldsm4(ah[mi], bA + ao);
            }
            int brow = (lane & 7) + ((lane >> 4) << 3);
            int bkch = kk + (((lane >> 3) & 1) << 3);
#pragma unroll
            for (int npi = 0; npi < 4; npi++) {
                uint32_t bo =
                    (uint32_t)((wn + npi * 16 + brow) * SLD + bkch) * 2;
                uint32_t bb[4];
                ldsm4(bb, bB + bo);
                int n0i = npi * 2, n1i = npi * 2 + 1;
#pragma unroll
                for (int mi = 0; mi < 4; mi++) {
                    mma16816(acc[mi][n0i], ah[mi], bb[0], bb[1]);
                    mma16816(acc[mi][n1i], ah[mi], bb[2], bb[3]);
                }
            }
        }
        __syncthreads();
    }

    // epilogue: convert fp32 acc -> fp16 storage
#pragma unroll
    for (int mi = 0; mi < 4; mi++) {
        int row = m0 + wm + 16 * mi + g;
#pragma unroll
        for (int ni = 0; ni < 8; ni++) {
            int nc = n0 + wn + ni * 8 + t * 2;
            __half* baseh = (nc < 256) ? g_xlh : g_xrh;
            int col = nc & 255;
            *(__half2*)&baseh[(size_t)row * 256 + col] =
                __floats2half2_rn(acc[mi][ni][0], acc[mi][ni][1]);
            *(__half2*)&baseh[(size_t)(row + 8) * 256 + col] =
                __floats2half2_rn(acc[mi][ni][2], acc[mi][ni][3]);
        }
    }
}

// ============================================================
// CSR construction  (edge_index int32: row 0 = src, row 1 = dst)
// ============================================================
__global__ void zero_cnt_k(int M)
{
    int i = blockIdx.x * blockDim.x + threadIdx.x;
    if (i < M) g_cnt[i] = 0;
}

__global__ void count_k(const int* __restrict__ ei, int E)
{
    int e = blockIdx.x * blockDim.x + threadIdx.x;
    if (e < E) atomicAdd(&g_cnt[ei[E + e]], 1);
}

__global__ void scan1_k(int M)
{
    __shared__ int s[1024];
    int gi = blockIdx.x * 1024 + threadIdx.x;
    int v = (gi < M) ? g_cnt[gi] : 0;
    s[threadIdx.x] = v;
    __syncthreads();
#pragma unroll
    for (int off = 1; off < 1024; off <<= 1) {
        int tv = (threadIdx.x >= off) ? s[threadIdx.x - off] : 0;
        __syncthreads();
        s[threadIdx.x] += tv;
        __syncthreads();
    }
    if (gi < M) g_incl[gi] = s[threadIdx.x];
    if (threadIdx.x == 1023) g_bsum[blockIdx.x] = s[1023];
}

__global__ void scan2_k(int nb)
{
    if (threadIdx.x == 0 && blockIdx.x == 0) {
        int run = 0;
        for (int b = 0; b < nb; b++) { int tv = g_bsum[b]; g_bsum[b] = run; run += tv; }
    }
}

__global__ void scan3_k(int M)
{
    int i = blockIdx.x * blockDim.x + threadIdx.x;
    if (i < M) {
        int incl = g_incl[i] + g_bsum[i >> 10];
        g_incl[i] = incl;
        g_cursor[i] = incl - g_cnt[i];
    }
}

__global__ void scatter_k(const int* __restrict__ ei, int E)
{
    int e = blockIdx.x * blockDim.x + threadIdx.x;
    if (e < E) {
        int d = ei[E + e];
        int pos = atomicAdd(&g_cursor[d], 1);
        g_srcs[pos] = ei[e];
    }
}

// ============================================================
// GATv2 attention + aggregation, one warp per dst node.
// Lane l owns channels 8l..8l+7 (head l>>3), fp16 rows.
// m=0 softmax, half2 scores, 4-edge unroll (MLP=4 gathers).
// ============================================================
__device__ __forceinline__ float score_h2(uint4 xlr, const __half2 xr2[4],
                                          const __half2 at2[4], __half2 c02)
{
    const __half2* xl2 = (const __half2*)&xlr;
    __half2 p2;
#pragma unroll
    for (int k = 0; k < 4; k++) {
        __half2 z = __hadd2(xl2[k], xr2[k]);
        __half2 lz = __hmax2(z, __hmul2(z, c02));
        p2 = (k == 0) ? __hmul2(at2[0], lz) : __hfma2(at2[k], lz, p2);
    }
    float2 pf = __half22float2(p2);
    return pf.x + pf.y;
}

__device__ __forceinline__ void h8_to_f8(uint4 r, float4& A, float4& B)
{
    __half2* h = (__half2*)&r;
    float2 f0 = __half22float2(h[0]);
    float2 f1 = __half22float2(h[1]);
    float2 f2 = __half22float2(h[2]);
    float2 f3 = __half22float2(h[3]);
    A = make_float4(f0.x, f0.y, f1.x, f1.y);
    B = make_float4(f2.x, f2.y, f3.x, f3.y);
}

__global__ void __launch_bounds__(256)
agg_k(const float* __restrict__ att, const float* __restrict__ bias,
      float* __restrict__ out, int M)
{
    const int gwarp = (blockIdx.x * blockDim.x + threadIdx.x) >> 5;
    const int lane = threadIdx.x & 31;
    if (gwarp >= M) return;
    const int i = gwarp;
    const int c0 = lane * 8;
    const __half2 c02 = __float2half2_rn(NEG_SLOPE);

    __half2 at2[4];
#pragma unroll
    for (int k = 0; k < 4; k++) {
        float2 a = *(const float2*)&att[c0 + 2 * k];
        at2[k] = __floats2half2_rn(a.x, a.y);
    }
    uint4 xr_raw = *(const uint4*)(g_xrh + (size_t)i * D_IN + c0);
    __half2 xr2[4];
#pragma unroll
    for (int k = 0; k < 4; k++) xr2[k] = ((const __half2*)&xr_raw)[k];

    float d = 0.f;
    float4 accA = make_float4(0.f, 0.f, 0.f, 0.f);
    float4 accB = make_float4(0.f, 0.f, 0.f, 0.f);

    auto one = [&](uint4 raw) {
        float p = score_h2(raw, xr2, at2, c02);
        p += __shfl_xor_sync(0xffffffffu, p, 1);
        p += __shfl_xor_sync(0xffffffffu, p, 2);
        p += __shfl_xor_sync(0xffffffffu, p, 4);
        float w = __expf(fminf(p, 60.f));
        float4 xlA, xlB;
        h8_to_f8(raw, xlA, xlB);
        d += w;
        accA.x += w * xlA.x; accA.y += w * xlA.y;
        accA.z += w * xlA.z; accA.w += w * xlA.w;
        accB.x += w * xlB.x; accB.y += w * xlB.y;
        accB.z += w * xlB.z; accB.w += w * xlB.w;
    };

    // self loop
    one(*(const uint4*)(g_xlh + (size_t)i * D_IN + c0));

    const int end = g_incl[i];
    int j = end - g_cnt[i];

    // remainder (cnt mod 4)
    while (((end - j) & 3) != 0) {
        int src = g_srcs[j];
        one(*(const uint4*)(g_xlh + (size_t)src * D_IN + c0));
        j++;
    }

    // quads: 4 independent gathers in flight
    for (; j < end; j += 4) {
        int s0 = g_srcs[j],     s1 = g_srcs[j + 1];
        int s2 = g_srcs[j + 2], s3 = g_srcs[j + 3];
        uint4 r0 = *(const uint4*)(g_xlh + (size_t)s0 * D_IN + c0);
        uint4 r1 = *(const uint4*)(g_xlh + (size_t)s1 * D_IN + c0);
        uint4 r2 = *(const uint4*)(g_xlh + (size_t)s2 * D_IN + c0);
        uint4 r3 = *(const uint4*)(g_xlh + (size_t)s3 * D_IN + c0);
        float p0 = score_h2(r0, xr2, at2, c02);
        float p1 = score_h2(r1, xr2, at2, c02);
        float p2 = score_h2(r2, xr2, at2, c02);
        float p3 = score_h2(r3, xr2, at2, c02);
#pragma unroll
        for (int o = 1; o <= 4; o <<= 1) {
            p0 += __shfl_xor_sync(0xffffffffu, p0, o);
            p1 += __shfl_xor_sync(0xffffffffu, p1, o);
            p2 += __shfl_xor_sync(0xffffffffu, p2, o);
            p3 += __shfl_xor_sync(0xffffffffu, p3, o);
        }
        float w0 = __expf(fminf(p0, 60.f));
        float w1 = __expf(fminf(p1, 60.f));
        float w2 = __expf(fminf(p2, 60.f));
        float w3 = __expf(fminf(p3, 60.f));
        float4 aA, aB, bA, bB, cA, cB, dA, dB;
        h8_to_f8(r0, aA, aB);
        h8_to_f8(r1, bA, bB);
        h8_to_f8(r2, cA, cB);
        h8_to_f8(r3, dA, dB);
        d += (w0 + w1) + (w2 + w3);
        accA.x += (w0 * aA.x + w1 * bA.x) + (w2 * cA.x + w3 * dA.x);
        accA.y += (w0 * aA.y + w1 * bA.y) + (w2 * cA.y + w3 * dA.y);
        accA.z += (w0 * aA.z + w1 * bA.z) + (w2 * cA.z + w3 * dA.z);
        accA.w += (w0 * aA.w + w1 * bA.w) + (w2 * cA.w + w3 * dA.w);
        accB.x += (w0 * aB.x + w1 * bB.x) + (w2 * cB.x + w3 * dB.x);
        accB.y += (w0 * aB.y + w1 * bB.y) + (w2 * cB.y + w3 * dB.y);
        accB.z += (w0 * aB.z + w1 * bB.z) + (w2 * cB.z + w3 * dB.z);
        accB.w += (w0 * aB.w + w1 * bB.w) + (w2 * cB.w + w3 * dB.w);
    }

    float inv = 1.f / (d + 1e-16f);
    float z[8] = { accA.x * inv, accA.y * inv, accA.z * inv, accA.w * inv,
                   accB.x * inv, accB.y * inv, accB.z * inv, accB.w * inv };
#pragma unroll
    for (int q = 0; q < 8; q++) {
        z[q] += __shfl_xor_sync(0xffffffffu, z[q], 8);
        z[q] += __shfl_xor_sync(0xffffffffu, z[q], 16);
    }

    if (lane < 8) {
#pragma unroll
        for (int q = 0; q < 8; q++) {
            float o = 0.25f * z[q] + bias[c0 + q];
            z[q] = o > 0.f ? o : expm1f(o);
        }
        float* dst = out + (size_t)i * D_OUT + c0;
        *(float4*)dst = make_float4(z[0], z[1], z[2], z[3]);
        *(float4*)(dst + 4) = make_float4(z[4], z[5], z[6], z[7]);
    }
}

// ============================================================
extern "C" void kernel_launch(void* const* d_in, const int* in_sizes, int n_in,
                              void* d_out, int out_size)
{
    const int* ei        = (const int*)d_in[1];
    const float* emb     = (const float*)d_in[2];
    const float* Wl      = (const float*)d_in[3];
    const float* Wr      = (const float*)d_in[4];
    const float* att     = (const float*)d_in[5];
    const float* bias    = (const float*)d_in[6];
    float* out           = (float*)d_out;

    const int E = in_sizes[1] / 2;         // 1,600,000
    const int M = in_sizes[2] / D_IN;      // 100,000
    const int T = (M + 127) / 128;         // 782 row tiles
    const int MP = T * 128;

    const int GEMM_SMEM = 2 * STAGE_B;     // 73728 B
    static int smem_set = 0;
    if (!smem_set) {
        cudaFuncSetAttribute(gemm_mma, cudaFuncAttributeMaxDynamicSharedMemorySize,
                             GEMM_SMEM);
        smem_set = 1;
    }

    int tb = 256;
    int n4 = M * 64, np4 = MP * 64;
    int nb = (M + 1023) / 1024;

    // single stream; gemm_mma kept in profile slot 4
    prepA_k<<<(np4 + 255) / 256, 256>>>((const float4*)emb, n4, np4);   // 1
    prepW_k<<<512, 256>>>(Wl, Wr);                                      // 2
    zero_cnt_k<<<(M + tb - 1) / tb, tb>>>(M);                           // 3
    gemm_mma<<<dim3(4, T), 128, GEMM_SMEM>>>();                         // 4
    count_k<<<(E + tb - 1) / tb, tb>>>(ei, E);                          // 5
    scan1_k<<<nb, 1024>>>(M);                                           // 6
    scan2_k<<<1, 32>>>(nb);                                             // 7
    scan3_k<<<(M + tb - 1) / tb, tb>>>(M);                              // 8
    scatter_k<<<(E + tb - 1) / tb, tb>>>(ei, E);                        // 9
    agg_k<<<(M + 7) / 8, 256>>>(att, bias, out, M);                     // 10

    (void)n_in; (void)out_size;
}

// round 17
// speedup vs baseline: 1.0854x; 1.0854x over previous
#include <cuda_runtime.h>
#include <cuda_fp16.h>
#include <cstdint>

#define N_NODE   100000
#define NODE_PAD 100096
#define D_IN     256
#define D_OUT    64
#define E_MAX    1600000
#define NEG_SLOPE 0.2f
#define SLD 72   // smem row stride in fp16 elems (144B) for 64-wide k stages

// ---- scratch (__device__ globals; no allocation at runtime) ----
__device__ __half g_xlh[NODE_PAD * D_IN];   // emb @ W_l, fp16
__device__ __half g_xrh[NODE_PAD * D_IN];   // emb @ W_r, fp16
__device__ __half g_Af[NODE_PAD * D_IN];    // emb, fp16
__device__ __half g_Bf[512 * 256];          // rows 0-255: Wl^T, 256-511: Wr^T ([n][k])
__device__ int   g_cnt[N_NODE];
__device__ int   g_incl[N_NODE];
__device__ int   g_cursor[N_NODE];
__device__ int   g_srcs[E_MAX];
__device__ int   g_bsum[256];

// ============================================================
// Prep: fp32 -> fp16
// ============================================================
__global__ void prepA_k(const float4* __restrict__ emb4, int n4, int np4)
{
    int i = blockIdx.x * blockDim.x + threadIdx.x;
    if (i >= np4) return;
    float4 v = (i < n4) ? emb4[i] : make_float4(0.f, 0.f, 0.f, 0.f);
    __half2* hp = (__half2*)g_Af;
    hp[2 * i]     = __floats2half2_rn(v.x, v.y);
    hp[2 * i + 1] = __floats2half2_rn(v.z, v.w);
}

__global__ void prepW_k(const float* __restrict__ Wl, const float* __restrict__ Wr)
{
    int idx = blockIdx.x * blockDim.x + threadIdx.x;   // 512*256
    if (idx >= 512 * 256) return;
    int n = idx >> 8, k = idx & 255;
    float v = (n < 256) ? Wl[k * 256 + n] : Wr[k * 256 + (n - 256)];
    g_Bf[idx] = __float2half_rn(v);
}

// ============================================================
// mma.sync fp16 GEMM, cp.async double-buffered (64-wide k stages),
// ldmatrix frags. C[NODE_PAD,512] = A x [Wl|Wr]^T, fp32 accum.
// CTA 128m x 128n, 4 warps of 64x64 (2x2), 2 CTAs/SM. (R16 config)
// ============================================================
__device__ __forceinline__ void mma16816(float c[4], const uint32_t a[4],
                                         const uint32_t b0, const uint32_t b1)
{
    asm volatile(
        "mma.sync.aligned.m16n8k16.row.col.f32.f16.f16.f32 "
        "{%0,%1,%2,%3}, {%4,%5,%6,%7}, {%8,%9}, {%0,%1,%2,%3};"
        : "+f"(c[0]), "+f"(c[1]), "+f"(c[2]), "+f"(c[3])
        : "r"(a[0]), "r"(a[1]), "r"(a[2]), "r"(a[3]), "r"(b0), "r"(b1));
}

__device__ __forceinline__ void ldsm4(uint32_t r[4], uint32_t addr)
{
    asm volatile("ldmatrix.sync.aligned.m8n8.x4.shared.b16 {%0,%1,%2,%3}, [%4];"
                 : "=r"(r[0]), "=r"(r[1]), "=r"(r[2]), "=r"(r[3]) : "r"(addr));
}

__device__ __forceinline__ void cpa16(uint32_t dst, const void* src)
{
    asm volatile("cp.async.ca.shared.global [%0], [%1], 16;"
                 :: "r"(dst), "l"(src));
}

#define TILE_MAT (128 * SLD * 2)   // 18432 B per matrix tile (128 rows x 64 k)
#define STAGE_B  (2 * TILE_MAT)    // 36864 B (A + B)
#define OFF_A 0
#define OFF_B TILE_MAT

__global__ void __launch_bounds__(128, 2)
gemm_mma()
{
    extern __shared__ __align__(16) char smem[];
    uint32_t sb;
    asm("{ .reg .u64 t; cvta.to.shared.u64 t, %1; cvt.u32.u64 %0, t; }"
        : "=r"(sb) : "l"(smem));

    const int tid = threadIdx.x;
    const int wid = tid >> 5;          // 0..3
    const int lane = tid & 31;
    const int g = lane >> 2;
    const int t = lane & 3;
    const int m0 = blockIdx.y * 128;
    const int n0 = blockIdx.x * 128;
    const int wm = (wid & 1) * 64;     // warp row base
    const int wn = (wid >> 1) * 64;    // warp col base

    float acc[4][8][4];
#pragma unroll
    for (int i = 0; i < 4; i++)
#pragma unroll
        for (int j = 0; j < 8; j++)
#pragma unroll
            for (int q = 0; q < 4; q++) acc[i][j][q] = 0.f;

    // stage: 128 rows x 64 fp16 per matrix = 1024 uint4; 8 chunks/thread
    auto stage_load = [&](int s, int kt) {
        uint32_t st = sb + s * STAGE_B;
#pragma unroll
        for (int i = 0; i < 8; i++) {
            int idx = tid + i * 128;
            int r = idx >> 3, q = idx & 7;
            size_t ga = (size_t)(m0 + r) * 256 + kt * 64 + q * 8;
            size_t gb = (size_t)(n0 + r) * 256 + kt * 64 + q * 8;
            uint32_t so = (uint32_t)(r * SLD + q * 8) * 2;
            cpa16(st + OFF_A + so, g_Af + ga);
            cpa16(st + OFF_B + so, g_Bf + gb);
        }
        asm volatile("cp.async.commit_group;" ::: "memory");
    };

    stage_load(0, 0);

    for (int kt = 0; kt < 4; kt++) {
        if (kt < 3) {
            stage_load((kt + 1) & 1, kt + 1);
            asm volatile("cp.async.wait_group 1;" ::: "memory");
        } else {
            asm volatile("cp.async.wait_group 0;" ::: "memory");
        }
        __syncthreads();

        uint32_t st = sb + (kt & 1) * STAGE_B;
        uint32_t bA = st + OFF_A, bB = st + OFF_B;

#pragma unroll
        for (int kk = 0; kk < 64; kk += 16) {
            uint32_t ah[4][4];
            int arow = (lane & 15);
            int akch = kk + ((lane >> 4) << 3);
#pragma unroll
            for (int mi = 0; mi < 4; mi++) {
                uint32_t ao = (uint32_t)((wm + mi * 16 + arow) * SLD + akch) * 2;
                ldsm4(ah[mi], bA + ao);
            }
            int brow = (lane & 7) + ((lane >> 4) << 3);
            int bkch = kk + (((lane >> 3) & 1) << 3);
#pragma unroll
            for (int npi = 0; npi < 4; npi++) {
                uint32_t bo =
                    (uint32_t)((wn + npi * 16 + brow) * SLD + bkch) * 2;
                uint32_t bb[4];
                ldsm4(bb, bB + bo);
                int n0i = npi * 2, n1i = npi * 2 + 1;
#pragma unroll
                for (int mi = 0; mi < 4; mi++) {
                    mma16816(acc[mi][n0i], ah[mi], bb[0], bb[1]);
                    mma16816(acc[mi][n1i], ah[mi], bb[2], bb[3]);
                }
            }
        }
        __syncthreads();
    }

    // epilogue: convert fp32 acc -> fp16 storage
#pragma unroll
    for (int mi = 0; mi < 4; mi++) {
        int row = m0 + wm + 16 * mi + g;
#pragma unroll
        for (int ni = 0; ni < 8; ni++) {
            int nc = n0 + wn + ni * 8 + t * 2;
            __half* baseh = (nc < 256) ? g_xlh : g_xrh;
            int col = nc & 255;
            *(__half2*)&baseh[(size_t)row * 256 + col] =
                __floats2half2_rn(acc[mi][ni][0], acc[mi][ni][1]);
            *(__half2*)&baseh[(size_t)(row + 8) * 256 + col] =
                __floats2half2_rn(acc[mi][ni][2], acc[mi][ni][3]);
        }
    }
}

// ============================================================
// CSR construction  (edge_index int32: row 0 = src, row 1 = dst)
// ============================================================
__global__ void zero_cnt_k(int M)
{
    int i = blockIdx.x * blockDim.x + threadIdx.x;
    if (i < M) g_cnt[i] = 0;
}

__global__ void count_k(const int* __restrict__ ei, int E)
{
    int e = blockIdx.x * blockDim.x + threadIdx.x;
    if (e < E) atomicAdd(&g_cnt[ei[E + e]], 1);
}

__global__ void scan1_k(int M)
{
    __shared__ int s[1024];
    int gi = blockIdx.x * 1024 + threadIdx.x;
    int v = (gi < M) ? g_cnt[gi] : 0;
    s[threadIdx.x] = v;
    __syncthreads();
#pragma unroll
    for (int off = 1; off < 1024; off <<= 1) {
        int tv = (threadIdx.x >= off) ? s[threadIdx.x - off] : 0;
        __syncthreads();
        s[threadIdx.x] += tv;
        __syncthreads();
    }
    if (gi < M) g_incl[gi] = s[threadIdx.x];
    if (threadIdx.x == 1023) g_bsum[blockIdx.x] = s[1023];
}

__global__ void scan2_k(int nb)
{
    if (threadIdx.x == 0 && blockIdx.x == 0) {
        int run = 0;
        for (int b = 0; b < nb; b++) { int tv = g_bsum[b]; g_bsum[b] = run; run += tv; }
    }
}

__global__ void scan3_k(int M)
{
    int i = blockIdx.x * blockDim.x + threadIdx.x;
    if (i < M) {
        int incl = g_incl[i] + g_bsum[i >> 10];
        g_incl[i] = incl;
        g_cursor[i] = incl - g_cnt[i];
    }
}

__global__ void scatter_k(const int* __restrict__ ei, int E)
{
    int e = blockIdx.x * blockDim.x + threadIdx.x;
    if (e < E) {
        int d = ei[E + e];
        int pos = atomicAdd(&g_cursor[d], 1);
        g_srcs[pos] = ei[e];
    }
}

// ============================================================
// GATv2 attention + aggregation, one warp per dst node.
// Lane l owns channels 8l..8l+7 (head l>>3), fp16 rows.
// m=0 softmax, half2 scores, pair loop. (R15 config)
// ============================================================
__device__ __forceinline__ float score_h2(uint4 xlr, const __half2 xr2[4],
                                          const __half2 at2[4], __half2 c02)
{
    const __half2* xl2 = (const __half2*)&xlr;
    __half2 p2;
#pragma unroll
    for (int k = 0; k < 4; k++) {
        __half2 z = __hadd2(xl2[k], xr2[k]);
        __half2 lz = __hmax2(z, __hmul2(z, c02));
        p2 = (k == 0) ? __hmul2(at2[0], lz) : __hfma2(at2[k], lz, p2);
    }
    float2 pf = __half22float2(p2);
    return pf.x + pf.y;
}

__device__ __forceinline__ void h8_to_f8(uint4 r, float4& A, float4& B)
{
    __half2* h = (__half2*)&r;
    float2 f0 = __half22float2(h[0]);
    float2 f1 = __half22float2(h[1]);
    float2 f2 = __half22float2(h[2]);
    float2 f3 = __half22float2(h[3]);
    A = make_float4(f0.x, f0.y, f1.x, f1.y);
    B = make_float4(f2.x, f2.y, f3.x, f3.y);
}

__global__ void __launch_bounds__(256)
agg_k(const float* __restrict__ att, const float* __restrict__ bias,
      float* __restrict__ out, int M)
{
    const int gwarp = (blockIdx.x * blockDim.x + threadIdx.x) >> 5;
    const int lane = threadIdx.x & 31;
    if (gwarp >= M) return;
    const int i = gwarp;
    const int c0 = lane * 8;
    const __half2 c02 = __float2half2_rn(NEG_SLOPE);

    __half2 at2[4];
#pragma unroll
    for (int k = 0; k < 4; k++) {
        float2 a = *(const float2*)&att[c0 + 2 * k];
        at2[k] = __floats2half2_rn(a.x, a.y);
    }
    uint4 xr_raw = *(const uint4*)(g_xrh + (size_t)i * D_IN + c0);
    __half2 xr2[4];
#pragma unroll
    for (int k = 0; k < 4; k++) xr2[k] = ((const __half2*)&xr_raw)[k];

    float d = 0.f;
    float4 accA = make_float4(0.f, 0.f, 0.f, 0.f);
    float4 accB = make_float4(0.f, 0.f, 0.f, 0.f);

    auto one = [&](uint4 raw) {
        float p = score_h2(raw, xr2, at2, c02);
        p += __shfl_xor_sync(0xffffffffu, p, 1);
        p += __shfl_xor_sync(0xffffffffu, p, 2);
        p += __shfl_xor_sync(0xffffffffu, p, 4);
        float w = __expf(fminf(p, 60.f));
        float4 xlA, xlB;
        h8_to_f8(raw, xlA, xlB);
        d += w;
        accA.x += w * xlA.x; accA.y += w * xlA.y;
        accA.z += w * xlA.z; accA.w += w * xlA.w;
        accB.x += w * xlB.x; accB.y += w * xlB.y;
        accB.z += w * xlB.z; accB.w += w * xlB.w;
    };

    // self loop
    one(*(const uint4*)(g_xlh + (size_t)i * D_IN + c0));

    const int end = g_incl[i];
    int j = end - g_cnt[i];
    const int cnt = end - j;

    if (cnt & 1) {
        int src = g_srcs[j];
        one(*(const uint4*)(g_xlh + (size_t)src * D_IN + c0));
        j++;
    }

    // pairs: interleaved loads, scores, reductions; independent updates
    for (; j < end; j += 2) {
        int s0 = g_srcs[j];
        int s1 = g_srcs[j + 1];
        uint4 r0 = *(const uint4*)(g_xlh + (size_t)s0 * D_IN + c0);
        uint4 r1 = *(const uint4*)(g_xlh + (size_t)s1 * D_IN + c0);
        float p0 = score_h2(r0, xr2, at2, c02);
        float p1 = score_h2(r1, xr2, at2, c02);
        p0 += __shfl_xor_sync(0xffffffffu, p0, 1);
        p1 += __shfl_xor_sync(0xffffffffu, p1, 1);
        p0 += __shfl_xor_sync(0xffffffffu, p0, 2);
        p1 += __shfl_xor_sync(0xffffffffu, p1, 2);
        p0 += __shfl_xor_sync(0xffffffffu, p0, 4);
        p1 += __shfl_xor_sync(0xffffffffu, p1, 4);
        float w0 = __expf(fminf(p0, 60.f));
        float w1 = __expf(fminf(p1, 60.f));
        float4 aA, aB, bA, bB;
        h8_to_f8(r0, aA, aB);
        h8_to_f8(r1, bA, bB);
        d += w0 + w1;
        accA.x += w0 * aA.x + w1 * bA.x;
        accA.y += w0 * aA.y + w1 * bA.y;
        accA.z += w0 * aA.z + w1 * bA.z;
        accA.w += w0 * aA.w + w1 * bA.w;
        accB.x += w0 * aB.x + w1 * bB.x;
        accB.y += w0 * aB.y + w1 * bB.y;
        accB.z += w0 * aB.z + w1 * bB.z;
        accB.w += w0 * aB.w + w1 * bB.w;
    }

    float inv = 1.f / (d + 1e-16f);
    float z[8] = { accA.x * inv, accA.y * inv, accA.z * inv, accA.w * inv,
                   accB.x * inv, accB.y * inv, accB.z * inv, accB.w * inv };
#pragma unroll
    for (int q = 0; q < 8; q++) {
        z[q] += __shfl_xor_sync(0xffffffffu, z[q], 8);
        z[q] += __shfl_xor_sync(0xffffffffu, z[q], 16);
    }

    if (lane < 8) {
#pragma unroll
        for (int q = 0; q < 8; q++) {
            float o = 0.25f * z[q] + bias[c0 + q];
            z[q] = o > 0.f ? o : expm1f(o);
        }
        float* dst = out + (size_t)i * D_OUT + c0;
        *(float4*)dst = make_float4(z[0], z[1], z[2], z[3]);
        *(float4*)(dst + 4) = make_float4(z[4], z[5], z[6], z[7]);
    }
}

// ============================================================
extern "C" void kernel_launch(void* const* d_in, const int* in_sizes, int n_in,
                              void* d_out, int out_size)
{
    const int* ei        = (const int*)d_in[1];
    const float* emb     = (const float*)d_in[2];
    const float* Wl      = (const float*)d_in[3];
    const float* Wr      = (const float*)d_in[4];
    const float* att     = (const float*)d_in[5];
    const float* bias    = (const float*)d_in[6];
    float* out           = (float*)d_out;

    const int E = in_sizes[1] / 2;         // 1,600,000
    const int M = in_sizes[2] / D_IN;      // 100,000
    const int T = (M + 127) / 128;         // 782 row tiles
    const int MP = T * 128;

    const int GEMM_SMEM = 2 * STAGE_B;     // 73728 B
    static int smem_set = 0;
    if (!smem_set) {
        cudaFuncSetAttribute(gemm_mma, cudaFuncAttributeMaxDynamicSharedMemorySize,
                             GEMM_SMEM);
        smem_set = 1;
    }

    int tb = 256;
    int n4 = M * 64, np4 = MP * 64;
    int nb = (M + 1023) / 1024;

    // single stream; gemm_mma kept in profile slot 4
    prepA_k<<<(np4 + 255) / 256, 256>>>((const float4*)emb, n4, np4);   // 1
    prepW_k<<<512, 256>>>(Wl, Wr);                                      // 2
    zero_cnt_k<<<(M + tb - 1) / tb, tb>>>(M);                           // 3
    gemm_mma<<<dim3(4, T), 128, GEMM_SMEM>>>();                         // 4
    count_k<<<(E + tb - 1) / tb, tb>>>(ei, E);                          // 5
    scan1_k<<<nb, 1024>>>(M);                                           // 6
    scan2_k<<<1, 32>>>(nb);                                             // 7
    scan3_k<<<(M + tb - 1) / tb, tb>>>(M);                              // 8
    scatter_k<<<(E + tb - 1) / tb, tb>>>(ei, E);                        // 9
    agg_k<<<(M + 7) / 8, 256>>>(att, bias, out, M);                     // 10

    (void)n_in; (void)out_size;
}